// round 13
// baseline (speedup 1.0000x reference)
#include <cuda_runtime.h>
#include <cstdint>

#define N2    361
#define NTHR  384
#define TS    512
#define OVF   24
#define NEGV  (-1000000000.0f)
#define I32MIN_V (-2147483647 - 1)
#define GRIDB 592                     // 148 SMs * 4 resident blocks

__global__ __launch_bounds__(NTHR, 4)
void board_kernel(const float* __restrict__ logits,
                  const int* __restrict__ legal,      // bool as int32
                  const int* __restrict__ player,
                  const int* __restrict__ cur_hash,
                  const int* __restrict__ hist,
                  const int* __restrict__ move_count,
                  const int* __restrict__ ZposT,
                  const int* __restrict__ sgi,
                  const int* __restrict__ cap,
                  float* __restrict__ out,
                  int B)
{
    __shared__ int sh_tab[3][TS];     // triple-buffered exact table (6 KB)
    __shared__ int sh_gx[3][8];
    __shared__ int sh_ovf[3][OVF];
    __shared__ int sh_ovfn[3];
    __shared__ int sh_zd[2][N2];      // delta tables: [0]=ze^zb, [1]=ze^zw

    const int t   = threadIdx.x;
    const bool w11 = ((t >> 5) == 11);
    const int l   = t & 31;

    for (int i = t; i < N2; i += NTHR) {
        const int ze = ZposT[i];
        sh_zd[0][i] = ze ^ ZposT[N2 + i];
        sh_zd[1][i] = ze ^ ZposT[2 * N2 + i];
    }
    for (int i = t; i < 3 * TS / 4; i += NTHR)
        reinterpret_cast<int4*>(sh_tab)[i] = make_int4(-1, -1, -1, -1);
    if (t < 3) sh_ovfn[t] = 0;
    __syncthreads();

    const int g  = gridDim.x;
    const int b0 = blockIdx.x;

    // prefetch hist/sgi for the first insert board
    int h_cur = 0, sg_cur = 0;
    if (b0 < B) {
        if (t < N2) h_cur = __ldcs(hist + b0 * N2 + t);
        if (w11)    sg_cur = __ldcs(sgi + b0 * 32 + l);
    }

    // carried pipeline state
    int  key1 = 0;  bool ins1 = false;    // inserted last iter (pending CAS-fix)
    int  key2 = 0;  bool ins2 = false;    // inserted 2 iters ago (pending clear)
    int  ch_c = 0, pl_c = 0, mc_c = 0;    // scalars of last-inserted board
    int  Pi = 0;                          // buffer hosting this iter's insert

    for (int bf = b0 - g; bf < B; bf += g) {
        const int bi = bf + g;                       // board inserted this iter
        const int Pf = (Pi == 0) ? 2 : Pi - 1;       // buffer of bf
        const int Pc = (Pi == 2) ? 0 : Pi + 1;       // buffer to clear (bf - g)

        // ---- streaming loads for the board we probe this iteration (bf) ----
        int4  c4 = make_int4(-1, -1, -1, -1);
        float lg = 0.0f;
        int   lgl = 0;
        if (bf >= 0 && t < N2) {
            const int idx = bf * N2 + t;
            c4  = __ldcs(reinterpret_cast<const int4*>(cap) + idx);
            lg  = __ldcs(logits + idx);
            lgl = __ldcs(legal + idx);
        }
        const int ch_f = ch_c, pl_f = pl_c, mc_f = mc_c;

        // ---- insert-side work for bi ----
        int pl_i = 0, mc_i = 0, ch_i = 0;
        int h_nxt = 0, sg_nxt = 0;
        int key0 = 0; bool ins0 = false;
        if (bi < B) {
            pl_i = player[bi] & 1;
            ch_i = cur_hash[bi];
            mc_i = move_count[bi];
            if (mc_i < 0) mc_i = 0;
            if (mc_i > N2 - 1) mc_i = N2 - 1;        // mc < 361 per setup

            const int bn = bi + g;                   // prefetch next insert board
            if (bn < B) {
                if (t < N2) h_nxt = __ldcs(hist + bn * N2 + t);
                if (w11)    sg_nxt = __ldcs(sgi + bn * 32 + l);
            }

            if (w11) {                               // fused group-XOR for bi
                int si = sg_cur;
                si = si < 0 ? 0 : (si >= N2 ? N2 - 1 : si);
                int d = sh_zd[1 - pl_i][si];         // z_opp ^ z_empty
                d ^= __shfl_xor_sync(0xffffffffu, d, 1);
                d ^= __shfl_xor_sync(0xffffffffu, d, 2);
                if ((l & 3) == 0) sh_gx[Pi][l >> 2] = d;
            }

            if (t <= mc_i) {                         // pass-1 STS insert
                ins0 = true;
                key0 = (t < mc_i) ? h_cur : I32MIN_V;
                const unsigned hs = (unsigned)key0 * 2654435761u;
                sh_tab[Pi][hs >> 23] = key0;         // losses healed next iter
            }
        }

        // ---- CAS-fix for bf (its pass-1 was last iter, barrier-ordered) ----
        if (ins1) {
            const unsigned hs = (unsigned)key1 * 2654435761u;
            const int s1 = (int)(hs >> 23);
            if (sh_tab[Pf][s1] != key1) {
                const int s2 = (int)((hs >> 12) & (TS - 1));
                int prev = atomicCAS(&sh_tab[Pf][s2], -1, key1);
                if (prev != -1 && prev != key1) {
                    const int s3 = (int)((hs ^ (hs >> 9)) & (TS - 1));
                    prev = atomicCAS(&sh_tab[Pf][s3], -1, key1);
                    if (prev != -1 && prev != key1) {
                        const int oi = atomicAdd(&sh_ovfn[Pf], 1);
                        if (oi < OVF) sh_ovf[Pf][oi] = key1;
                    }
                }
            }
        }

        __syncthreads();   // THE barrier: bf's table complete; old probes done

        // ---- probe bf + output ----
        if (bf >= 0 && t < N2) {
            int cd = 0;
            if (c4.x >= 0) cd ^= sh_gx[Pf][c4.x & 7];
            if (c4.y >= 0) cd ^= sh_gx[Pf][c4.y & 7];
            if (c4.z >= 0) cd ^= sh_gx[Pf][c4.z & 7];
            if (c4.w >= 0) cd ^= sh_gx[Pf][c4.w & 7];

            const int cand = ch_f ^ sh_zd[pl_f][t] ^ cd;

            const unsigned hh = (unsigned)cand * 2654435761u;
            bool rep = (sh_tab[Pf][hh >> 23] == cand) |
                       (sh_tab[Pf][(hh >> 12) & (TS - 1)] == cand) |
                       (sh_tab[Pf][(hh ^ (hh >> 9)) & (TS - 1)] == cand);

            int ovn = sh_ovfn[Pf];
            const bool fbk = (ovn > OVF);            // statistically unreachable
            if (ovn > OVF) ovn = OVF;
            for (int i2 = 0; i2 < ovn; ++i2) rep |= (sh_ovf[Pf][i2] == cand);
            if (fbk && !rep) {                        // exact global fallback
                rep = (cand == I32MIN_V);
                for (int q = 0; q < mc_f && !rep; ++q)
                    rep = (hist[bf * N2 + q] == cand);
            }

            __stcs(out + bf * N2 + t, ((lgl != 0) & !rep) ? lg : NEGV);
        }

        // ---- clear buffer Pc (board bf-g; its probes were last iteration) ----
        if (ins2) {
            const unsigned hs = (unsigned)key2 * 2654435761u;
            sh_tab[Pc][hs >> 23] = -1;
            sh_tab[Pc][(hs >> 12) & (TS - 1)] = -1;
            sh_tab[Pc][(hs ^ (hs >> 9)) & (TS - 1)] = -1;
        }
        if (t == 0) sh_ovfn[Pc] = 0;

        // ---- rotate pipeline state ----
        key2 = key1; ins2 = ins1;
        key1 = key0; ins1 = ins0;
        ch_c = ch_i; pl_c = pl_i; mc_c = mc_i;
        h_cur = h_nxt; sg_cur = sg_nxt;
        Pi = (Pi == 2) ? 0 : Pi + 1;
    }
}

extern "C" void kernel_launch(void* const* d_in, const int* in_sizes, int n_in,
                              void* d_out, int out_size)
{
    const float* logits = (const float*)d_in[0];
    const int*   legal  = (const int*)d_in[1];
    const int*   player = (const int*)d_in[2];
    const int*   chash  = (const int*)d_in[3];
    const int*   hist   = (const int*)d_in[4];
    const int*   mcnt   = (const int*)d_in[5];
    const int*   zpos   = (const int*)d_in[6];
    const int*   sgi    = (const int*)d_in[7];
    const int*   cap    = (const int*)d_in[10];
    float*       out    = (float*)d_out;

    const int B = in_sizes[2];           // current_player: B elements

    board_kernel<<<GRIDB, NTHR>>>(logits, legal, player, chash, hist, mcnt,
                                  zpos, sgi, cap, out, B);
}

// round 14
// speedup vs baseline: 4.1669x; 4.1669x over previous
#include <cuda_runtime.h>
#include <cstdint>

#define N2    361
#define NTHR  384
#define TS    1024
#define OVF   16
#define NEGV  (-1000000000.0f)
#define I32MIN_V (-2147483647 - 1)
#define GRIDB 740                     // 148 SMs * 5 resident blocks

__global__ __launch_bounds__(NTHR, 5)
void board_kernel(const float* __restrict__ logits,
                  const int* __restrict__ legal,      // bool as int32
                  const int* __restrict__ player,
                  const int* __restrict__ cur_hash,
                  const int* __restrict__ hist,
                  const int* __restrict__ move_count,
                  const int* __restrict__ ZposT,
                  const int* __restrict__ sgi,
                  const int* __restrict__ cap,
                  float* __restrict__ out,
                  int B)
{
    __shared__ int sh_tab[2][TS];     // double-buffered exact table
    __shared__ int sh_gx[2][8];
    __shared__ int sh_ovf[2][OVF];
    __shared__ int sh_ovfn[2];
    __shared__ int sh_zd[2][N2];      // delta tables: [0]=ze^zb, [1]=ze^zw

    const int t = threadIdx.x;
    const bool w11 = ((t >> 5) == 11);
    const int l = t & 31;

    for (int i = t; i < N2; i += NTHR) {
        const int ze = ZposT[i];
        sh_zd[0][i] = ze ^ ZposT[N2 + i];
        sh_zd[1][i] = ze ^ ZposT[2 * N2 + i];
    }
    for (int i = t; i < 2 * TS / 4; i += NTHR)
        reinterpret_cast<int4*>(sh_tab)[i] = make_int4(-1, -1, -1, -1);
    if (t < 2) sh_ovfn[t] = 0;
    __syncthreads();

    // per-buffer clear state (slots written 2 boards ago)
    bool cl_ins0 = false, cl_ins1 = false;
    int  cl0_1 = 0, cl0_2 = 0, cl0_3 = 0;
    int  cl1_1 = 0, cl1_2 = 0, cl1_3 = 0;

    const int g = gridDim.x;

    // prologue prefetch for first board
    int h_cur = 0, sg_cur = 0;
    {
        const int b0 = blockIdx.x;
        if (b0 < B) {
            if (t < N2) h_cur = __ldcs(hist + b0 * N2 + t);
            if (w11)    sg_cur = __ldcs(sgi + b0 * 32 + l);
        }
    }

#define BODY(P, BCUR, BNXT, CLI, CL1, CL2, CL3)                                  \
    {                                                                            \
        const int pl = player[BCUR] & 1;                                         \
        const int ch = cur_hash[BCUR];                                           \
        int mc = move_count[BCUR];                                               \
        if (mc < 0) mc = 0;                                                      \
        if (mc > N2 - 1) mc = N2 - 1;                                            \
        const int idx = (BCUR) * N2 + t;                                         \
        int4 c4 = make_int4(-1, -1, -1, -1);                                     \
        float lg = 0.0f; int lgl = 0;                                            \
        if (t < N2) {                                                            \
            c4  = __ldcs(reinterpret_cast<const int4*>(cap) + idx);              \
            lg  = __ldcs(logits + idx);                                          \
            lgl = __ldcs(legal + idx);                                           \
        }                                                                        \
        int h_nxt = 0, sg_nxt = 0;                                               \
        if ((BNXT) < B) {                                                        \
            if (t < N2) h_nxt = __ldcs(hist + (BNXT) * N2 + t);                  \
            if (w11)    sg_nxt = __ldcs(sgi + (BNXT) * 32 + l);                  \
        }                                                                        \
        /* phase 1: clears + group XOR + pass-1 insert */                        \
        if (CLI) {                                                               \
            sh_tab[P][CL1] = -1; sh_tab[P][CL2] = -1; sh_tab[P][CL3] = -1;       \
        }                                                                        \
        if (t == 0) sh_ovfn[P] = 0;                                              \
        if (w11) {                                                               \
            int si = sg_cur;                                                     \
            si = si < 0 ? 0 : (si >= N2 ? N2 - 1 : si);                          \
            int d = sh_zd[1 - pl][si];                                           \
            d ^= __shfl_xor_sync(0xffffffffu, d, 1);                             \
            d ^= __shfl_xor_sync(0xffffffffu, d, 2);                             \
            if ((l & 3) == 0) sh_gx[P][l >> 2] = d;                              \
        }                                                                        \
        const bool ins = (t < mc);    /* no sentinel insert */                   \
        int key = 0; unsigned hsh = 0; int s1 = 0, s2 = 0, s3 = 0;               \
        if (ins) {                                                               \
            key = h_cur;                                                         \
            hsh = (unsigned)key * 2654435761u;                                   \
            s1 = (int)(hsh >> 22);                                               \
            s2 = (int)((hsh >> 12) & (TS - 1));                                  \
            s3 = (int)((hsh ^ (hsh >> 9)) & (TS - 1));                           \
            sh_tab[P][s1] = key;                                                 \
        }                                                                        \
        __syncthreads();                                                         \
        /* phase 2: readback -> CAS s2 -> CAS s3 -> overflow */                  \
        if (ins && sh_tab[P][s1] != key) {                                       \
            int prev = atomicCAS(&sh_tab[P][s2], -1, key);                       \
            if (prev != -1 && prev != key) {                                     \
                prev = atomicCAS(&sh_tab[P][s3], -1, key);                       \
                if (prev != -1 && prev != key) {                                 \
                    const int oi = atomicAdd(&sh_ovfn[P], 1);                    \
                    if (oi < OVF) sh_ovf[P][oi] = key;                           \
                }                                                                \
            }                                                                    \
        }                                                                        \
        __syncthreads();                                                         \
        /* phase 3: candidate + membership + output */                           \
        if (t < N2) {                                                            \
            int cd = 0;                                                          \
            if (c4.x >= 0) cd ^= sh_gx[P][c4.x & 7];                             \
            if (c4.y >= 0) cd ^= sh_gx[P][c4.y & 7];                             \
            if (c4.z >= 0) cd ^= sh_gx[P][c4.z & 7];                             \
            if (c4.w >= 0) cd ^= sh_gx[P][c4.w & 7];                             \
            const int cand = ch ^ sh_zd[pl][t] ^ cd;                             \
            const unsigned hh = (unsigned)cand * 2654435761u;                    \
            bool rep = (sh_tab[P][hh >> 22] == cand) |                           \
                       (sh_tab[P][(hh >> 12) & (TS - 1)] == cand) |              \
                       (sh_tab[P][(hh ^ (hh >> 9)) & (TS - 1)] == cand) |        \
                       (cand == I32MIN_V);  /* sentinel: mc < M always */        \
            int ovn = sh_ovfn[P];                                                \
            const bool fbk = (ovn > OVF);                                        \
            if (ovn > OVF) ovn = OVF;                                            \
            for (int i2 = 0; i2 < ovn; ++i2) rep |= (sh_ovf[P][i2] == cand);     \
            if (fbk && !rep) {                                                   \
                for (int q = 0; q < mc && !rep; ++q)                             \
                    rep = (hist[(BCUR) * N2 + q] == cand);                       \
            }                                                                    \
            __stcs(out + idx, ((lgl != 0) & !rep) ? lg : NEGV);                  \
        }                                                                        \
        CLI = ins; CL1 = s1; CL2 = s2; CL3 = s3;                                 \
        h_cur = h_nxt; sg_cur = sg_nxt;                                          \
    }

    for (int b = blockIdx.x; b < B; b += 2 * g) {
        BODY(0, b, b + g, cl_ins0, cl0_1, cl0_2, cl0_3)
        const int b1 = b + g;
        if (b1 < B) {
            BODY(1, b1, b1 + g, cl_ins1, cl1_1, cl1_2, cl1_3)
        }
    }
#undef BODY
}

extern "C" void kernel_launch(void* const* d_in, const int* in_sizes, int n_in,
                              void* d_out, int out_size)
{
    const float* logits = (const float*)d_in[0];
    const int*   legal  = (const int*)d_in[1];
    const int*   player = (const int*)d_in[2];
    const int*   chash  = (const int*)d_in[3];
    const int*   hist   = (const int*)d_in[4];
    const int*   mcnt   = (const int*)d_in[5];
    const int*   zpos   = (const int*)d_in[6];
    const int*   sgi    = (const int*)d_in[7];
    const int*   cap    = (const int*)d_in[10];
    float*       out    = (float*)d_out;

    const int B = in_sizes[2];           // current_player: B elements

    board_kernel<<<GRIDB, NTHR>>>(logits, legal, player, chash, hist, mcnt,
                                  zpos, sgi, cap, out, B);
}